// round 4
// baseline (speedup 1.0000x reference)
#include <cuda_runtime.h>
#include <cuda_fp16.h>
#include <math.h>

// ---------------------------------------------------------------------------
// GaussianSplatRenderer3D — B=4, N=32768, H=W=512, k=11 (121 taps)
// ONE red.global.add.noftz.v4.f16x2 per tap: [r*a, g*a | b*a, z*a | a, a | 0,0]
// No zero kernel: __device__ globals start zeroed; normalize restores zeros
// after reading, so the accumulator is zero at every splat entry (graph-safe,
// deterministic).
// ---------------------------------------------------------------------------

#define KTAP 11
#define MAXPIX (4 * 512 * 512)

static __device__ uint4 g_acc[MAXPIX];   // 8 x f16 per pixel; zero-init at load

__global__ void __launch_bounds__(128)
splat_kernel(const float* __restrict__ pos, const float* __restrict__ cov,
             const float* __restrict__ rgb, const float* __restrict__ opa,
             const float* __restrict__ Km,  const float* __restrict__ Rm,
             const float* __restrict__ tv,  int B, int N, int H, int W)
{
    int gid = blockIdx.x * blockDim.x + threadIdx.x;
    if (gid >= B * N) return;
    int b = gid / N;

    const float* Kb = Km + 9 * b;
    const float* Rb = Rm + 9 * b;
    const float* tb = tv + 3 * b;

    float p0 = pos[3 * gid + 0];
    float p1 = pos[3 * gid + 1];
    float p2 = pos[3 * gid + 2];

    // Xc = R @ p + t  (mul/add chain, no FMA contraction — matches XLA dot)
    float X = __fadd_rn(__fadd_rn(__fadd_rn(__fmul_rn(Rb[0], p0), __fmul_rn(Rb[1], p1)),
                                  __fmul_rn(Rb[2], p2)), tb[0]);
    float Y = __fadd_rn(__fadd_rn(__fadd_rn(__fmul_rn(Rb[3], p0), __fmul_rn(Rb[4], p1)),
                                  __fmul_rn(Rb[5], p2)), tb[1]);
    float Z = __fadd_rn(__fadd_rn(__fadd_rn(__fmul_rn(Rb[6], p0), __fmul_rn(Rb[7], p1)),
                                  __fmul_rn(Rb[8], p2)), tb[2]);

    float zs = fmaxf(Z, 1e-6f);
    float xs = __fdiv_rn(X, zs);
    float ys = __fdiv_rn(Y, zs);

    float u = __fadd_rn(__fadd_rn(__fmul_rn(Kb[0], xs), __fmul_rn(Kb[1], ys)), Kb[2]);
    float v = __fadd_rn(__fadd_rn(__fmul_rn(Kb[3], xs), __fmul_rn(Kb[4], ys)), Kb[5]);
    float fx = Kb[0];
    float fy = Kb[4];

    float sxx = cov[3 * gid + 0];
    float syy = cov[3 * gid + 1];
    float sx = __fdiv_rn(__fmul_rn(__fsqrt_rn(fmaxf(sxx, 1e-9f)), fx), zs);
    float sy = __fdiv_rn(__fmul_rn(__fsqrt_rn(fmaxf(syy, 1e-9f)), fy), zs);

    float o  = opa[gid];
    float cr = rgb[3 * gid + 0];
    float cg = rgb[3 * gid + 1];
    float cb = rgb[3 * gid + 2];

    // Packed per-gaussian constants: slot0 scale (r,g), slot1 scale (b,z)
    __half2 h_rg = __floats2half2_rn(cr, cg);
    __half2 h_bz = __floats2half2_rn(cb, Z);

    float isx = __fdiv_rn(1.f, fmaxf(sx, 1e-6f));
    float isy = __fdiv_rn(1.f, fmaxf(sy, 1e-6f));

    // Per-axis weights (0 for OOB -> tap skipped) and byte offsets
    float wxm[KTAP], wyo[KTAP];
    int   xoff[KTAP], yrow[KTAP];
#pragma unroll
    for (int i = 0; i < KTAP; ++i) {
        float off = (float)(i - KTAP / 2);
        float gx = __fmul_rn(off, isx);
        float gy = __fmul_rn(off, isy);
        float ewx = __expf(-0.5f * __fmul_rn(gx, gx));
        float ewy = __expf(-0.5f * __fmul_rn(gy, gy));
        int px = __float2int_rn(__fadd_rn(u, __fmul_rn(off, sx)));
        int py = __float2int_rn(__fadd_rn(v, __fmul_rn(off, sy)));
        bool okx = (px >= 0) & (px < W);
        bool oky = (py >= 0) & (py < H);
        wxm[i] = okx ? ewx : 0.f;
        wyo[i] = oky ? __fmul_rn(ewy, o) : 0.f;
        xoff[i] = px * 16;
        yrow[i] = py * W * 16;
    }

    char* baseb = (char*)g_acc + (size_t)b * (H * W) * 16;
#pragma unroll
    for (int j = 0; j < KTAP; ++j) {
        float wj = wyo[j];
        if (wj == 0.f) continue;
        char* rowp = baseb + yrow[j];
#pragma unroll
        for (int i = 0; i < KTAP; ++i) {
            float wi = wxm[i];
            if (wi == 0.f) continue;
            float a = __fmul_rn(wi, wj);
            __half2 a2 = __floats2half2_rn(a, a);
            __half2 v0 = __hmul2(h_rg, a2);   // (r*a, g*a)
            __half2 v1 = __hmul2(h_bz, a2);   // (b*a, z*a)
            unsigned r0 = *(unsigned*)&v0;
            unsigned r1 = *(unsigned*)&v1;
            unsigned r2 = *(unsigned*)&a2;    // (a, a) — free
            char* dst = rowp + xoff[i];
            asm volatile("red.global.add.noftz.v4.f16x2 [%0], {%1, %2, %3, %4};"
                         :: "l"(dst), "r"(r0), "r"(r1), "r"(r2), "r"(0u)
                         : "memory");
        }
    }
}

// Reads accumulator, writes outputs, and RESTORES ZEROS so the next
// kernel_launch (graph replay) sees a clean accumulator.
__global__ void normalize_kernel(float* __restrict__ out, int B, int H, int W) {
    int i = blockIdx.x * blockDim.x + threadIdx.x;
    int HW = H * W;
    int npix = B * HW;
    if (i >= npix) return;
    uint4 acc = g_acc[i];
    g_acc[i] = make_uint4(0u, 0u, 0u, 0u);
    __half2 h0 = *(__half2*)&acc.x;   // (r*a, g*a)
    __half2 h1 = *(__half2*)&acc.y;   // (b*a, z*a)
    __half2 h2 = *(__half2*)&acc.z;   // (a, a)
    float2 f0 = __half22float2(h0);
    float2 f1 = __half22float2(h1);
    float  fa = __low2float(h2);
    float den = fmaxf(fa, 1e-6f);
    float inv = __fdiv_rn(1.f, den);
    int b = i / HW;
    int pix = i - b * HW;
    float* rgbout = out + (size_t)b * 3 * HW + pix;
    rgbout[0]      = f0.x * inv;
    rgbout[HW]     = f0.y * inv;
    rgbout[2 * HW] = f1.x * inv;
    out[(size_t)B * 3 * HW + (size_t)b * HW + pix] = f1.y * inv;
}

extern "C" void kernel_launch(void* const* d_in, const int* in_sizes, int n_in,
                              void* d_out, int out_size)
{
    const float* pos = (const float*)d_in[0];
    const float* cov = (const float*)d_in[1];
    const float* rgb = (const float*)d_in[2];
    const float* opa = (const float*)d_in[3];
    const float* Km  = (const float*)d_in[4];
    const float* Rm  = (const float*)d_in[5];
    const float* tv  = (const float*)d_in[6];

    int B  = in_sizes[4] / 9;
    int N  = in_sizes[0] / (3 * B);
    int HW = out_size / (4 * B);
    int W  = (int)(sqrt((double)HW) + 0.5);
    int H  = HW / W;
    int npix = B * HW;

    int total = B * N;
    splat_kernel<<<(total + 127) / 128, 128>>>(pos, cov, rgb, opa, Km, Rm, tv, B, N, H, W);

    normalize_kernel<<<(npix + 255) / 256, 256>>>((float*)d_out, B, H, W);
}

// round 5
// speedup vs baseline: 1.1161x; 1.1161x over previous
#include <cuda_runtime.h>
#include <cuda_fp16.h>
#include <math.h>

// ---------------------------------------------------------------------------
// GaussianSplatRenderer3D — B=4, N=32768, H=W=512, k=11 (121 taps)
// zero (STG.128 stream) -> splat (ONE red.global.add.noftz.v4.f16x2 per tap:
// [r*a, g*a | b*a, z*a | a, a | 0, 0]) -> normalize (pure read+write).
// R4 lesson: fusing the zero-restore into normalize costs 37us (L2 RMW);
// a dedicated zero kernel costs 6us. Keep them separate.
// ---------------------------------------------------------------------------

#define KTAP 11
#define MAXPIX (4 * 512 * 512)

static __device__ uint4 g_acc[MAXPIX];   // 8 x f16 per pixel

__global__ void zero_kernel(int npix) {
    int stride = gridDim.x * blockDim.x;
    uint4 z = make_uint4(0u, 0u, 0u, 0u);
    for (int i = blockIdx.x * blockDim.x + threadIdx.x; i < npix; i += stride)
        g_acc[i] = z;
}

__global__ void __launch_bounds__(128)
splat_kernel(const float* __restrict__ pos, const float* __restrict__ cov,
             const float* __restrict__ rgb, const float* __restrict__ opa,
             const float* __restrict__ Km,  const float* __restrict__ Rm,
             const float* __restrict__ tv,  int B, int N, int H, int W)
{
    int gid = blockIdx.x * blockDim.x + threadIdx.x;
    if (gid >= B * N) return;
    int b = gid / N;

    const float* Kb = Km + 9 * b;
    const float* Rb = Rm + 9 * b;
    const float* tb = tv + 3 * b;

    float p0 = pos[3 * gid + 0];
    float p1 = pos[3 * gid + 1];
    float p2 = pos[3 * gid + 2];

    // Xc = R @ p + t  (mul/add chain, no FMA contraction — matches XLA dot)
    float X = __fadd_rn(__fadd_rn(__fadd_rn(__fmul_rn(Rb[0], p0), __fmul_rn(Rb[1], p1)),
                                  __fmul_rn(Rb[2], p2)), tb[0]);
    float Y = __fadd_rn(__fadd_rn(__fadd_rn(__fmul_rn(Rb[3], p0), __fmul_rn(Rb[4], p1)),
                                  __fmul_rn(Rb[5], p2)), tb[1]);
    float Z = __fadd_rn(__fadd_rn(__fadd_rn(__fmul_rn(Rb[6], p0), __fmul_rn(Rb[7], p1)),
                                  __fmul_rn(Rb[8], p2)), tb[2]);

    float zs = fmaxf(Z, 1e-6f);
    float xs = __fdiv_rn(X, zs);
    float ys = __fdiv_rn(Y, zs);

    float u = __fadd_rn(__fadd_rn(__fmul_rn(Kb[0], xs), __fmul_rn(Kb[1], ys)), Kb[2]);
    float v = __fadd_rn(__fadd_rn(__fmul_rn(Kb[3], xs), __fmul_rn(Kb[4], ys)), Kb[5]);
    float fx = Kb[0];
    float fy = Kb[4];

    float sxx = cov[3 * gid + 0];
    float syy = cov[3 * gid + 1];
    float sx = __fdiv_rn(__fmul_rn(__fsqrt_rn(fmaxf(sxx, 1e-9f)), fx), zs);
    float sy = __fdiv_rn(__fmul_rn(__fsqrt_rn(fmaxf(syy, 1e-9f)), fy), zs);

    float o  = opa[gid];
    float cr = rgb[3 * gid + 0];
    float cg = rgb[3 * gid + 1];
    float cb = rgb[3 * gid + 2];

    // Packed per-gaussian constants: slot0 scale (r,g), slot1 scale (b,z)
    __half2 h_rg = __floats2half2_rn(cr, cg);
    __half2 h_bz = __floats2half2_rn(cb, Z);

    float isx = __fdiv_rn(1.f, fmaxf(sx, 1e-6f));
    float isy = __fdiv_rn(1.f, fmaxf(sy, 1e-6f));

    // Per-axis weights (0 for OOB -> tap skipped) and byte offsets
    float wxm[KTAP], wyo[KTAP];
    int   xoff[KTAP], yrow[KTAP];
#pragma unroll
    for (int i = 0; i < KTAP; ++i) {
        float off = (float)(i - KTAP / 2);
        float gx = __fmul_rn(off, isx);
        float gy = __fmul_rn(off, isy);
        float ewx = __expf(-0.5f * __fmul_rn(gx, gx));
        float ewy = __expf(-0.5f * __fmul_rn(gy, gy));
        int px = __float2int_rn(__fadd_rn(u, __fmul_rn(off, sx)));
        int py = __float2int_rn(__fadd_rn(v, __fmul_rn(off, sy)));
        bool okx = (px >= 0) & (px < W);
        bool oky = (py >= 0) & (py < H);
        wxm[i] = okx ? ewx : 0.f;
        wyo[i] = oky ? __fmul_rn(ewy, o) : 0.f;
        xoff[i] = px * 16;
        yrow[i] = py * W * 16;
    }

    char* baseb = (char*)g_acc + (size_t)b * (H * W) * 16;
#pragma unroll
    for (int j = 0; j < KTAP; ++j) {
        float wj = wyo[j];
        if (wj == 0.f) continue;
        char* rowp = baseb + yrow[j];
#pragma unroll
        for (int i = 0; i < KTAP; ++i) {
            float wi = wxm[i];
            if (wi == 0.f) continue;
            float a = __fmul_rn(wi, wj);
            __half2 a2 = __floats2half2_rn(a, a);
            __half2 v0 = __hmul2(h_rg, a2);   // (r*a, g*a)
            __half2 v1 = __hmul2(h_bz, a2);   // (b*a, z*a)
            unsigned r0 = *(unsigned*)&v0;
            unsigned r1 = *(unsigned*)&v1;
            unsigned r2 = *(unsigned*)&a2;    // (a, a) — free
            char* dst = rowp + xoff[i];
            asm volatile("red.global.add.noftz.v4.f16x2 [%0], {%1, %2, %3, %4};"
                         :: "l"(dst), "r"(r0), "r"(r1), "r"(r2), "r"(0u)
                         : "memory");
        }
    }
}

__global__ void normalize_kernel(float* __restrict__ out, int B, int H, int W) {
    int i = blockIdx.x * blockDim.x + threadIdx.x;
    int HW = H * W;
    int npix = B * HW;
    if (i >= npix) return;
    uint4 acc = g_acc[i];
    __half2 h0 = *(__half2*)&acc.x;   // (r*a, g*a)
    __half2 h1 = *(__half2*)&acc.y;   // (b*a, z*a)
    __half2 h2 = *(__half2*)&acc.z;   // (a, a)
    float2 f0 = __half22float2(h0);
    float2 f1 = __half22float2(h1);
    float  fa = __low2float(h2);
    float den = fmaxf(fa, 1e-6f);
    float inv = __fdiv_rn(1.f, den);
    int b = i / HW;
    int pix = i - b * HW;
    float* rgbout = out + (size_t)b * 3 * HW + pix;
    rgbout[0]      = f0.x * inv;
    rgbout[HW]     = f0.y * inv;
    rgbout[2 * HW] = f1.x * inv;
    out[(size_t)B * 3 * HW + (size_t)b * HW + pix] = f1.y * inv;
}

extern "C" void kernel_launch(void* const* d_in, const int* in_sizes, int n_in,
                              void* d_out, int out_size)
{
    const float* pos = (const float*)d_in[0];
    const float* cov = (const float*)d_in[1];
    const float* rgb = (const float*)d_in[2];
    const float* opa = (const float*)d_in[3];
    const float* Km  = (const float*)d_in[4];
    const float* Rm  = (const float*)d_in[5];
    const float* tv  = (const float*)d_in[6];

    int B  = in_sizes[4] / 9;
    int N  = in_sizes[0] / (3 * B);
    int HW = out_size / (4 * B);
    int W  = (int)(sqrt((double)HW) + 0.5);
    int H  = HW / W;
    int npix = B * HW;

    zero_kernel<<<592, 256>>>(npix);

    int total = B * N;
    splat_kernel<<<(total + 127) / 128, 128>>>(pos, cov, rgb, opa, Km, Rm, tv, B, N, H, W);

    normalize_kernel<<<(npix + 255) / 256, 256>>>((float*)d_out, B, H, W);
}

// round 6
// speedup vs baseline: 1.1354x; 1.0173x over previous
#include <cuda_runtime.h>
#include <cuda_fp16.h>
#include <math.h>

// ---------------------------------------------------------------------------
// GaussianSplatRenderer3D — B=4, N=32768, H=W=512, k=11 (121 taps)
// zero (1 STG.128/thread) -> splat (ONE red.global.add.noftz.v4.f16x2 per
// tap, at the REDG lane floor ~62us) -> normalize (x4 vectorized, MLP=4).
// ---------------------------------------------------------------------------

#define KTAP 11
#define MAXPIX (4 * 512 * 512)

static __device__ uint4 g_acc[MAXPIX];   // 8 x f16 per pixel

__global__ void zero_kernel(int npix) {
    int i = blockIdx.x * blockDim.x + threadIdx.x;
    if (i < npix)
        g_acc[i] = make_uint4(0u, 0u, 0u, 0u);
}

__global__ void __launch_bounds__(128)
splat_kernel(const float* __restrict__ pos, const float* __restrict__ cov,
             const float* __restrict__ rgb, const float* __restrict__ opa,
             const float* __restrict__ Km,  const float* __restrict__ Rm,
             const float* __restrict__ tv,  int B, int N, int H, int W)
{
    int gid = blockIdx.x * blockDim.x + threadIdx.x;
    if (gid >= B * N) return;
    int b = gid / N;

    const float* Kb = Km + 9 * b;
    const float* Rb = Rm + 9 * b;
    const float* tb = tv + 3 * b;

    float p0 = pos[3 * gid + 0];
    float p1 = pos[3 * gid + 1];
    float p2 = pos[3 * gid + 2];

    // Xc = R @ p + t  (mul/add chain, no FMA contraction — matches XLA dot)
    float X = __fadd_rn(__fadd_rn(__fadd_rn(__fmul_rn(Rb[0], p0), __fmul_rn(Rb[1], p1)),
                                  __fmul_rn(Rb[2], p2)), tb[0]);
    float Y = __fadd_rn(__fadd_rn(__fadd_rn(__fmul_rn(Rb[3], p0), __fmul_rn(Rb[4], p1)),
                                  __fmul_rn(Rb[5], p2)), tb[1]);
    float Z = __fadd_rn(__fadd_rn(__fadd_rn(__fmul_rn(Rb[6], p0), __fmul_rn(Rb[7], p1)),
                                  __fmul_rn(Rb[8], p2)), tb[2]);

    float zs = fmaxf(Z, 1e-6f);
    float xs = __fdiv_rn(X, zs);
    float ys = __fdiv_rn(Y, zs);

    float u = __fadd_rn(__fadd_rn(__fmul_rn(Kb[0], xs), __fmul_rn(Kb[1], ys)), Kb[2]);
    float v = __fadd_rn(__fadd_rn(__fmul_rn(Kb[3], xs), __fmul_rn(Kb[4], ys)), Kb[5]);
    float fx = Kb[0];
    float fy = Kb[4];

    float sxx = cov[3 * gid + 0];
    float syy = cov[3 * gid + 1];
    float sx = __fdiv_rn(__fmul_rn(__fsqrt_rn(fmaxf(sxx, 1e-9f)), fx), zs);
    float sy = __fdiv_rn(__fmul_rn(__fsqrt_rn(fmaxf(syy, 1e-9f)), fy), zs);

    float o  = opa[gid];
    float cr = rgb[3 * gid + 0];
    float cg = rgb[3 * gid + 1];
    float cb = rgb[3 * gid + 2];

    // Packed per-gaussian constants: slot0 scale (r,g), slot1 scale (b,z)
    __half2 h_rg = __floats2half2_rn(cr, cg);
    __half2 h_bz = __floats2half2_rn(cb, Z);

    float isx = __fdiv_rn(1.f, fmaxf(sx, 1e-6f));
    float isy = __fdiv_rn(1.f, fmaxf(sy, 1e-6f));

    // Per-axis weights (0 for OOB -> tap skipped) and byte offsets
    float wxm[KTAP], wyo[KTAP];
    int   xoff[KTAP], yrow[KTAP];
#pragma unroll
    for (int i = 0; i < KTAP; ++i) {
        float off = (float)(i - KTAP / 2);
        float gx = __fmul_rn(off, isx);
        float gy = __fmul_rn(off, isy);
        float ewx = __expf(-0.5f * __fmul_rn(gx, gx));
        float ewy = __expf(-0.5f * __fmul_rn(gy, gy));
        int px = __float2int_rn(__fadd_rn(u, __fmul_rn(off, sx)));
        int py = __float2int_rn(__fadd_rn(v, __fmul_rn(off, sy)));
        bool okx = (px >= 0) & (px < W);
        bool oky = (py >= 0) & (py < H);
        wxm[i] = okx ? ewx : 0.f;
        wyo[i] = oky ? __fmul_rn(ewy, o) : 0.f;
        xoff[i] = px * 16;
        yrow[i] = py * W * 16;
    }

    char* baseb = (char*)g_acc + (size_t)b * (H * W) * 16;
#pragma unroll
    for (int j = 0; j < KTAP; ++j) {
        float wj = wyo[j];
        if (wj == 0.f) continue;
        char* rowp = baseb + yrow[j];
#pragma unroll
        for (int i = 0; i < KTAP; ++i) {
            float wi = wxm[i];
            if (wi == 0.f) continue;
            float a = __fmul_rn(wi, wj);
            __half2 a2 = __floats2half2_rn(a, a);
            __half2 v0 = __hmul2(h_rg, a2);   // (r*a, g*a)
            __half2 v1 = __hmul2(h_bz, a2);   // (b*a, z*a)
            unsigned r0 = *(unsigned*)&v0;
            unsigned r1 = *(unsigned*)&v1;
            unsigned r2 = *(unsigned*)&a2;    // (a, a) — free
            char* dst = rowp + xoff[i];
            asm volatile("red.global.add.noftz.v4.f16x2 [%0], {%1, %2, %3, %4};"
                         :: "l"(dst), "r"(r0), "r"(r1), "r"(r2), "r"(0u)
                         : "memory");
        }
    }
}

// x4 vectorized: each thread handles 4 consecutive pixels.
// 4 front-batched LDG.128 (MLP=4), then 4 coalesced STG.128 (one per channel).
// Requires HW % (4*256) == 0 (holds for 512x512); each block stays in one batch.
__global__ void __launch_bounds__(256)
normalize_kernel(float* __restrict__ out, int B, int H, int W) {
    int HW = H * W;
    int t = blockIdx.x * blockDim.x + threadIdx.x;   // quad index
    int nquad = (B * HW) >> 2;
    if (t >= nquad) return;
    int i0 = t << 2;                                  // first pixel of quad

    uint4 a0 = g_acc[i0 + 0];
    uint4 a1 = g_acc[i0 + 1];
    uint4 a2 = g_acc[i0 + 2];
    uint4 a3 = g_acc[i0 + 3];

    int b   = i0 / HW;
    int pix = i0 - b * HW;

    float4 r4, g4, b4, z4;
    {
        float2 f0 = __half22float2(*(__half2*)&a0.x);
        float2 f1 = __half22float2(*(__half2*)&a0.y);
        float inv = __fdiv_rn(1.f, fmaxf(__low2float(*(__half2*)&a0.z), 1e-6f));
        r4.x = f0.x * inv; g4.x = f0.y * inv; b4.x = f1.x * inv; z4.x = f1.y * inv;
    }
    {
        float2 f0 = __half22float2(*(__half2*)&a1.x);
        float2 f1 = __half22float2(*(__half2*)&a1.y);
        float inv = __fdiv_rn(1.f, fmaxf(__low2float(*(__half2*)&a1.z), 1e-6f));
        r4.y = f0.x * inv; g4.y = f0.y * inv; b4.y = f1.x * inv; z4.y = f1.y * inv;
    }
    {
        float2 f0 = __half22float2(*(__half2*)&a2.x);
        float2 f1 = __half22float2(*(__half2*)&a2.y);
        float inv = __fdiv_rn(1.f, fmaxf(__low2float(*(__half2*)&a2.z), 1e-6f));
        r4.z = f0.x * inv; g4.z = f0.y * inv; b4.z = f1.x * inv; z4.z = f1.y * inv;
    }
    {
        float2 f0 = __half22float2(*(__half2*)&a3.x);
        float2 f1 = __half22float2(*(__half2*)&a3.y);
        float inv = __fdiv_rn(1.f, fmaxf(__low2float(*(__half2*)&a3.z), 1e-6f));
        r4.w = f0.x * inv; g4.w = f0.y * inv; b4.w = f1.x * inv; z4.w = f1.y * inv;
    }

    float* rgbout = out + (size_t)b * 3 * HW + pix;
    *(float4*)(rgbout)          = r4;
    *(float4*)(rgbout + HW)     = g4;
    *(float4*)(rgbout + 2 * HW) = b4;
    *(float4*)(out + (size_t)B * 3 * HW + (size_t)b * HW + pix) = z4;
}

extern "C" void kernel_launch(void* const* d_in, const int* in_sizes, int n_in,
                              void* d_out, int out_size)
{
    const float* pos = (const float*)d_in[0];
    const float* cov = (const float*)d_in[1];
    const float* rgb = (const float*)d_in[2];
    const float* opa = (const float*)d_in[3];
    const float* Km  = (const float*)d_in[4];
    const float* Rm  = (const float*)d_in[5];
    const float* tv  = (const float*)d_in[6];

    int B  = in_sizes[4] / 9;
    int N  = in_sizes[0] / (3 * B);
    int HW = out_size / (4 * B);
    int W  = (int)(sqrt((double)HW) + 0.5);
    int H  = HW / W;
    int npix = B * HW;

    zero_kernel<<<(npix + 255) / 256, 256>>>(npix);

    int total = B * N;
    splat_kernel<<<(total + 127) / 128, 128>>>(pos, cov, rgb, opa, Km, Rm, tv, B, N, H, W);

    int nquad = npix >> 2;
    normalize_kernel<<<(nquad + 255) / 256, 256>>>((float*)d_out, B, H, W);
}